// round 12
// baseline (speedup 1.0000x reference)
#include <cuda_runtime.h>
#include <cuda_fp16.h>
#include <math.h>
#include <stdint.h>

// Problem constants
#define BB   2
#define SS   2048
#define HIDD 2048
#define HH   8
#define DD   256
#define HALF 128
#define NQKV 2560   // 2048 + 256 + 256 (fused Q,K,V projection)

// fp16 scratch (device globals; no allocation allowed)
__device__ __half g_hs16 [BB * SS * HIDD];
__device__ __half g_wqkv16[NQKV * HIDD];      // [Wq; Wk; Wv] stacked rows
__device__ __half g_wo16 [HIDD * HIDD];
__device__ float  g_bqkv [NQKV];
__device__ __half g_q16 [BB * SS * HH * DD];  // (b,s,h,d) flat (4096, 2048)
__device__ __half g_k16 [BB * SS * DD];       // flat (4096, 256)
__device__ __half g_v16 [BB * SS * DD];       // flat (4096, 256)
__device__ __half g_vt16[BB * DD * SS];       // (b,d,s) = V^T
__device__ __half g_p16 [(size_t)BB * HH * SS * SS];
__device__ __half g_oh16[BB * SS * HH * DD];  // flat (4096, 2048)

// ---------------------------------------------------------------------------
__device__ __forceinline__ uint32_t smem_u32(const void* p) {
    uint32_t a;
    asm("{ .reg .u64 t; cvta.to.shared.u64 t, %1; cvt.u32.u64 %0, t; }" : "=r"(a) : "l"(p));
    return a;
}
__device__ __forceinline__ void cpa16(uint32_t dst, const void* src) {
    asm volatile("cp.async.cg.shared.global [%0], [%1], 16;" :: "r"(dst), "l"(src) : "memory");
}
#define CP_COMMIT() asm volatile("cp.async.commit_group;" ::: "memory")

__device__ __forceinline__ void ldsm4(uint32_t r[4], uint32_t addr) {
    asm volatile("ldmatrix.sync.aligned.m8n8.x4.shared.b16 {%0,%1,%2,%3}, [%4];"
                 : "=r"(r[0]), "=r"(r[1]), "=r"(r[2]), "=r"(r[3]) : "r"(addr));
}
__device__ __forceinline__ void mma_f16(float c[4], const uint32_t a[4], const uint32_t* b) {
    asm volatile(
        "mma.sync.aligned.m16n8k16.row.col.f32.f16.f16.f32 "
        "{%0,%1,%2,%3}, {%4,%5,%6,%7}, {%8,%9}, {%0,%1,%2,%3};"
        : "+f"(c[0]), "+f"(c[1]), "+f"(c[2]), "+f"(c[3])
        : "r"(a[0]), "r"(a[1]), "r"(a[2]), "r"(a[3]), "r"(b[0]), "r"(b[1]));
}

// ---------------------------------------------------------------------------
// fp16 NT GEMM: C = alpha * A(M,K) @ B(N,K)^T + bias   (both operands k-contig)
//   MODE: 0 none, 1 column bias Add[n] (fp32),
//         3 fused Q|K|V routing (cols <2048 -> C, <2304 -> Ck, else -> Cv)
// Block 128x128x32, 256 threads (8 warps, 2x4), warp tile 64x32, occ 2.
// Double-buffered smem via cp.async; ldmatrix fragment loads.
// (identical mainloop to the proven round-8/11 kernel)
// ---------------------------------------------------------------------------
#define APITCH 80   // bytes per 32-half row (64B data + 16B pad)

template <typename CT, int MODE>
__global__ void __launch_bounds__(256, 2)
h_gemm(const __half* __restrict__ A, const __half* __restrict__ B,
       const float* __restrict__ Add, CT* __restrict__ C,
       __half* __restrict__ Ck, __half* __restrict__ Cv,
       int K, int lda, int ldb, int ldc, float alpha, int Hz,
       long aSB, long aSH, long bSB, long bSH, long cSB, long cSH, long addSB)
{
    __shared__ __align__(16) char smem[4 * 128 * APITCH + 512];
    const uint32_t sb = smem_u32(smem);
    const uint32_t AsS[2] = {sb,                  sb + 128 * APITCH};
    const uint32_t BsS[2] = {sb + 2*128*APITCH,   sb + 3*128*APITCH};
    float* add_s = (float*)(smem + 4 * 128 * APITCH);

    const int tid  = threadIdx.x;
    const int warp = tid >> 5, lane = tid & 31;
    const int gid  = lane >> 2, tid4 = lane & 3;
    const int wm0  = (warp >> 2) * 64;
    const int wn0  = (warp & 3) * 32;

    const int z  = blockIdx.z;
    const int zb = z / Hz;
    const int zh = z - zb * Hz;
    A += zb * aSB + zh * aSH;
    B += zb * bSB + zh * bSH;
    C += zb * cSB + zh * cSH;

    const int n0c = blockIdx.x * 128;
    if (MODE == 1 && tid < 128) add_s[tid] = Add[zb * addSB + n0c + tid];
    if (MODE == 3 && tid < 128) add_s[tid] = Add[n0c + tid];

    const __half* Ab = A + (long)(blockIdx.y * 128) * lda;
    const __half* Bb = B + (long)n0c * ldb;

    // cp.async mapping: 2 threads per row, 2x16B each
    const int lrow = tid >> 1;
    const int lch  = (tid & 1) * 16;   // halves offset (0 or 16)

    const int nIt = K / 32;

    // fragment smem addresses
    const uint32_t aoff = (uint32_t)((wm0 + (lane & 15)) * APITCH + (lane >> 4) * 16);
    const uint32_t boff = (uint32_t)((wn0 + (lane & 7) + ((lane >> 4) & 1) * 8) * APITCH
                                     + ((lane >> 3) & 1) * 16);

    float c[4][4][4];
    #pragma unroll
    for (int im = 0; im < 4; im++)
        #pragma unroll
        for (int in = 0; in < 4; in++)
            #pragma unroll
            for (int r = 0; r < 4; r++) c[im][in][r] = 0.f;

    // prologue: fetch tiles 0, 1
    #pragma unroll
    for (int p = 0; p < 2; p++) {
        const int k0 = p * 32;
        const uint32_t da = AsS[p] + lrow * APITCH + lch * 2;
        const uint32_t db = BsS[p] + lrow * APITCH + lch * 2;
        cpa16(da,      Ab + (long)lrow * lda + k0 + lch);
        cpa16(da + 16, Ab + (long)lrow * lda + k0 + lch + 8);
        cpa16(db,      Bb + (long)lrow * ldb + k0 + lch);
        cpa16(db + 16, Bb + (long)lrow * ldb + k0 + lch + 8);
        CP_COMMIT();
    }

    for (int it = 0; it < nIt; ++it) {
        const int buf = it & 1;
        if (it + 1 < nIt) asm volatile("cp.async.wait_group 1;" ::: "memory");
        else              asm volatile("cp.async.wait_group 0;" ::: "memory");
        __syncthreads();

        // compute on buf
        #pragma unroll
        for (int kk = 0; kk < 32; kk += 16) {
            uint32_t af[4][4], bf[2][4];
            #pragma unroll
            for (int im = 0; im < 4; im++)
                ldsm4(af[im], AsS[buf] + aoff + im * (16 * APITCH) + kk * 2);
            #pragma unroll
            for (int ng = 0; ng < 2; ng++)
                ldsm4(bf[ng], BsS[buf] + boff + ng * (16 * APITCH) + kk * 2);
            #pragma unroll
            for (int im = 0; im < 4; im++)
                #pragma unroll
                for (int in = 0; in < 4; in++)
                    mma_f16(c[im][in], af[im], &bf[in >> 1][(in & 1) * 2]);
        }
        __syncthreads();

        // fetch tile it+2 into buf
        if (it + 2 < nIt) {
            const int k0 = (it + 2) * 32;
            const uint32_t da = AsS[buf] + lrow * APITCH + lch * 2;
            const uint32_t db = BsS[buf] + lrow * APITCH + lch * 2;
            cpa16(da,      Ab + (long)lrow * lda + k0 + lch);
            cpa16(da + 16, Ab + (long)lrow * lda + k0 + lch + 8);
            cpa16(db,      Bb + (long)lrow * ldb + k0 + lch);
            cpa16(db + 16, Bb + (long)lrow * ldb + k0 + lch + 8);
            CP_COMMIT();
        }
    }

    // ---- epilogue ----
    const int m0 = blockIdx.y * 128 + wm0;

    // MODE 3: route to q / k / v; boundaries (2048, 2304) are 128-aligned
    __half* Cp16 = nullptr; int ldc3 = 0; int nbase3 = 0;
    if (MODE == 3) {
        if (n0c < 2048)      { Cp16 = (__half*)C; ldc3 = 2048; nbase3 = n0c; }
        else if (n0c < 2304) { Cp16 = Ck;         ldc3 = 256;  nbase3 = n0c - 2048; }
        else                 { Cp16 = Cv;         ldc3 = 256;  nbase3 = n0c - 2304; }
    }

    #pragma unroll
    for (int im = 0; im < 4; im++) {
        const long r0 = m0 + im * 16 + gid;
        #pragma unroll
        for (int in = 0; in < 4; in++) {
            const int lc = wn0 + in * 8 + tid4 * 2;     // local col in [0,128)
            float b0 = 0.f, b1 = 0.f;
            if (MODE == 1 || MODE == 3) { b0 = add_s[lc]; b1 = add_s[lc + 1]; }
            float v0 = c[im][in][0] * alpha + b0;
            float v1 = c[im][in][1] * alpha + b1;
            float v2 = c[im][in][2] * alpha + b0;
            float v3 = c[im][in][3] * alpha + b1;
            if (MODE == 3) {
                *(__half2*)&Cp16[r0 * ldc3 + nbase3 + lc]       = __floats2half2_rn(v0, v1);
                *(__half2*)&Cp16[(r0 + 8) * ldc3 + nbase3 + lc] = __floats2half2_rn(v2, v3);
            } else if (sizeof(CT) == 4) {
                float* Cp = (float*)C;
                *(float2*)&Cp[r0 * ldc + n0c + lc]       = make_float2(v0, v1);
                *(float2*)&Cp[(r0 + 8) * ldc + n0c + lc] = make_float2(v2, v3);
            } else {
                __half* Cp = (__half*)C;
                *(__half2*)&Cp[r0 * ldc + n0c + lc]       = __floats2half2_rn(v0, v1);
                *(__half2*)&Cp[(r0 + 8) * ldc + n0c + lc] = __floats2half2_rn(v2, v3);
            }
        }
    }
}

// ---------------------------------------------------------------------------
// V transpose: v16 (b*s, d) -> vt16 (b, d, s). 32x32 tiles via smem.
// ---------------------------------------------------------------------------
__global__ void transpose_v(const __half* __restrict__ v, __half* __restrict__ vt)
{
    __shared__ __half tile[32][33];
    const int s0 = blockIdx.x * 32;
    const int d0 = blockIdx.y * 32;
    const int b  = blockIdx.z;
    const int tx = threadIdx.x;        // 0..31
    const int ty = threadIdx.y;        // 0..7
    #pragma unroll
    for (int r = 0; r < 4; r++) {
        int s = s0 + ty + r * 8;
        tile[ty + r * 8][tx] = v[((long)b * SS + s) * DD + d0 + tx];
    }
    __syncthreads();
    #pragma unroll
    for (int r = 0; r < 4; r++) {
        int d = d0 + ty + r * 8;
        vt[((long)b * DD + d) * SS + s0 + tx] = tile[tx][ty + r * 8];
    }
}

// ---------------------------------------------------------------------------
// fp32 -> fp16 convert (n % 1024 == 0)
// ---------------------------------------------------------------------------
__global__ void f2h_kernel(const float* __restrict__ src, __half* __restrict__ dst, int n)
{
    int i = (blockIdx.x * 256 + threadIdx.x) * 4;
    if (i < n) {
        float4 v = *(const float4*)(src + i);
        *(__half2*)(dst + i)     = __floats2half2_rn(v.x, v.y);
        *(__half2*)(dst + i + 2) = __floats2half2_rn(v.z, v.w);
    }
}

// bias concat [bq(2048); bk(256); bv(256)] -> g_bqkv
__global__ void bias_concat(const float* __restrict__ bq, const float* __restrict__ bk,
                            const float* __restrict__ bv, float* __restrict__ dst)
{
    int i = blockIdx.x * 256 + threadIdx.x;
    if (i < 2048)      dst[i] = bq[i];
    else if (i < 2304) dst[i] = bk[i - 2048];
    else if (i < NQKV) dst[i] = bv[i - 2304];
}

// ---------------------------------------------------------------------------
// RoPE in fp16 (fast transcendental path): in-place on q (B*S*H rows) and
// k (B*S rows). 128 threads per row.
// ---------------------------------------------------------------------------
#define LOG2_THETA_OVER_HALF 0.1038102540010327f   // log2(10000)/128

__global__ void rope_kernel(__half* __restrict__ q, __half* __restrict__ k,
                            const int* __restrict__ pos)
{
    int bid = blockIdx.x;
    const int NQ = BB * SS * HH;
    __half* ptr;
    int b, s;
    if (bid < NQ) {
        int h = bid % HH;
        s = (bid / HH) % SS;
        b = bid / (HH * SS);
        ptr = q + (((long)(b * SS + s)) * HH + h) * DD;
    } else {
        int idx = bid - NQ;
        s = idx % SS;
        b = idx / SS;
        ptr = k + ((long)(b * SS + s)) * DD;
    }
    int i = threadIdx.x;                       // 0..127
    float p = (float)pos[b * SS + s];
    float inv = exp2f(-(float)i * LOG2_THETA_OVER_HALF);
    float fr = p * inv;
    float cs, sn;
    __sincosf(fr, &sn, &cs);
    float x1 = __half2float(ptr[i]);
    float x2 = __half2float(ptr[i + HALF]);
    ptr[i]        = __float2half_rn(cs * x1 - sn * x2);
    ptr[i + HALF] = __float2half_rn(sn * x1 + cs * x2);
}

// ---------------------------------------------------------------------------
// Row softmax over last dim (S=2048), vectorized 16B accesses.
// 256 threads per row; thread t owns 8 contiguous floats at t*8.
// Writes fp32 (output) and fp16 copy.
// ---------------------------------------------------------------------------
__global__ void softmax_kernel(float* __restrict__ attn, __half* __restrict__ p16)
{
    long row = blockIdx.x;
    float* p = attn + row * (long)SS;
    __half* ph = p16 + row * (long)SS;
    int t = threadIdx.x;

    float4 va = *(float4*)(p + t * 8);
    float4 vb = *(float4*)(p + t * 8 + 4);

    float m = fmaxf(fmaxf(fmaxf(va.x, va.y), fmaxf(va.z, va.w)),
                    fmaxf(fmaxf(vb.x, vb.y), fmaxf(vb.z, vb.w)));
    #pragma unroll
    for (int o = 16; o > 0; o >>= 1) m = fmaxf(m, __shfl_xor_sync(0xffffffffu, m, o));
    __shared__ float smax[8];
    __shared__ float ssum[8];
    if ((t & 31) == 0) smax[t >> 5] = m;
    __syncthreads();
    float bm = smax[0];
    #pragma unroll
    for (int i = 1; i < 8; i++) bm = fmaxf(bm, smax[i]);

    va.x = __expf(va.x - bm); va.y = __expf(va.y - bm);
    va.z = __expf(va.z - bm); va.w = __expf(va.w - bm);
    vb.x = __expf(vb.x - bm); vb.y = __expf(vb.y - bm);
    vb.z = __expf(vb.z - bm); vb.w = __expf(vb.w - bm);
    float sum = (va.x + va.y) + (va.z + va.w) + (vb.x + vb.y) + (vb.z + vb.w);
    #pragma unroll
    for (int o = 16; o > 0; o >>= 1) sum += __shfl_xor_sync(0xffffffffu, sum, o);
    if ((t & 31) == 0) ssum[t >> 5] = sum;
    __syncthreads();
    float tot = 0.f;
    #pragma unroll
    for (int i = 0; i < 8; i++) tot += ssum[i];
    float invs = 1.0f / tot;

    va.x *= invs; va.y *= invs; va.z *= invs; va.w *= invs;
    vb.x *= invs; vb.y *= invs; vb.z *= invs; vb.w *= invs;

    *(float4*)(p + t * 8)     = va;
    *(float4*)(p + t * 8 + 4) = vb;

    union { uint4 u; __half2 h[4]; } hv;
    hv.h[0] = __floats2half2_rn(va.x, va.y);
    hv.h[1] = __floats2half2_rn(va.z, va.w);
    hv.h[2] = __floats2half2_rn(vb.x, vb.y);
    hv.h[3] = __floats2half2_rn(vb.z, vb.w);
    *(uint4*)(ph + t * 8) = hv.u;
}

// ---------------------------------------------------------------------------
extern "C" void kernel_launch(void* const* d_in, const int* in_sizes, int n_in,
                              void* d_out, int out_size)
{
    const float* hs   = (const float*)d_in[0];
    const float* mask = (const float*)d_in[1];
    const int*   pos  = (const int*)  d_in[2];
    const float* Wq   = (const float*)d_in[3];
    const float* bq   = (const float*)d_in[4];
    const float* Wk   = (const float*)d_in[5];
    const float* bk   = (const float*)d_in[6];
    const float* Wv   = (const float*)d_in[7];
    const float* bv   = (const float*)d_in[8];
    const float* Wo   = (const float*)d_in[9];
    const float* bo   = (const float*)d_in[10];

    float* out  = (float*)d_out;                               // (B,S,HID)
    float* attn = out + (size_t)BB * SS * HIDD;                // (B,H,S,S)

    __half *hs16, *wqkv16, *wo16, *q16, *k16, *v16, *vt16, *p16, *oh16;
    float* bqkv;
    cudaGetSymbolAddress((void**)&hs16,   g_hs16);
    cudaGetSymbolAddress((void**)&wqkv16, g_wqkv16);
    cudaGetSymbolAddress((void**)&wo16,   g_wo16);
    cudaGetSymbolAddress((void**)&bqkv,   g_bqkv);
    cudaGetSymbolAddress((void**)&q16,    g_q16);
    cudaGetSymbolAddress((void**)&k16,    g_k16);
    cudaGetSymbolAddress((void**)&v16,    g_v16);
    cudaGetSymbolAddress((void**)&vt16,   g_vt16);
    cudaGetSymbolAddress((void**)&p16,    g_p16);
    cudaGetSymbolAddress((void**)&oh16,   g_oh16);

    dim3 blk(256);
    const int M = BB * SS;          // 4096

    // fp16 conversions (Wq, Wk, Wv stacked into one buffer)
    f2h_kernel<<<(BB * SS * HIDD) / 1024, 256>>>(hs, hs16, BB * SS * HIDD);
    f2h_kernel<<<(HIDD * HIDD) / 1024, 256>>>(Wq, wqkv16, HIDD * HIDD);
    f2h_kernel<<<(DD * HIDD) / 1024, 256>>>(Wk, wqkv16 + (size_t)2048 * HIDD, DD * HIDD);
    f2h_kernel<<<(DD * HIDD) / 1024, 256>>>(Wv, wqkv16 + (size_t)2304 * HIDD, DD * HIDD);
    f2h_kernel<<<(HIDD * HIDD) / 1024, 256>>>(Wo, wo16, HIDD * HIDD);
    bias_concat<<<NQKV / 256, 256>>>(bq, bk, bv, bqkv);

    // fused Q|K|V projection: (4096 x 2560) = hs @ [Wq;Wk;Wv]^T + bqkv
    h_gemm<__half, 3><<<dim3(NQKV / 128, M / 128, 1), blk>>>(
        hs16, wqkv16, bqkv, q16, k16, v16,
        HIDD, HIDD, HIDD, 0, 1.0f, 1, 0, 0, 0, 0, 0, 0, 0);

    // vT (b,d,s) from v16 (b*s, d)
    transpose_v<<<dim3(SS / 32, DD / 32, BB), dim3(32, 8)>>>(v16, vt16);

    // RoPE on q16, k16
    rope_kernel<<<BB * SS * HH + BB * SS, 128>>>(q16, k16, pos);

    // scores = (q @ k^T) * D^-0.5 + mask -> attn (fp32, output)
    h_gemm<float, 1><<<dim3(SS / 128, SS / 128, BB * HH), blk>>>(
        q16, k16, mask, attn, nullptr, nullptr,
        DD, HIDD, DD, SS, 0.0625f, HH,
        (long)SS * HIDD, (long)DD,
        (long)SS * DD,   0,
        (long)HH * SS * SS, (long)SS * SS,
        (long)SS);

    // softmax -> attn (fp32) + p16 (fp16)
    softmax_kernel<<<BB * HH * SS, 256>>>(attn, p16);

    // oh = P @ vT^T (NT with B = vT) -> oh16 (b, s, h*D)
    h_gemm<__half, 0><<<dim3(DD / 128, SS / 128, BB * HH), blk>>>(
        p16, vt16, nullptr, oh16, nullptr, nullptr,
        SS, SS, SS, HIDD, 1.0f, HH,
        (long)HH * SS * SS, (long)SS * SS,
        (long)DD * SS, 0,
        (long)SS * HIDD, (long)DD,
        0);

    // out = oh @ Wo^T + bo -> fp32
    h_gemm<float, 1><<<dim3(HIDD / 128, M / 128, 1), blk>>>(
        oh16, wo16, bo, out, nullptr, nullptr,
        HIDD, HIDD, HIDD, HIDD, 1.0f, 1, 0, 0, 0, 0, 0, 0, 0);
}